// round 1
// baseline (speedup 1.0000x reference)
#include <cuda_runtime.h>
#include <math.h>

// Problem dims (fixed by the reference)
#define Bv 32
#define Tv 128
#define Fv 64
#define Hv 64
#define HP 65            // padded row stride for [32][64] state tiles (bank-conflict-free)
#define NTHREADS 256

// ---------------------------------------------------------------------------
// Scratch (allocation-free): transposed inputs + precomputed time terms
// ---------------------------------------------------------------------------
__device__ float g_xT[Tv*Fv*Bv];   // x   -> [t][f][b]
__device__ float g_lT[Tv*Fv*Bv];   // l   -> [t][f][b]
__device__ float g_Tm[Tv*Fv*Bv];   // 1/log(t+e)
__device__ float g_sTm[Tv*Fv*Bv];  // sigmoid(Tm)
__device__ float g_fw[Tv*Bv];      // sum_f exp(-0.5*freq[b,t,f])

struct KParams { const float* p[30]; };

// ---------------------------------------------------------------------------
// Prologue: transpose + time precompute + cross-feature freq reduction
// grid = B*T blocks, 64 threads (one per feature)
// ---------------------------------------------------------------------------
__global__ void prologue_kernel(KParams prm) {
    int b  = blockIdx.x >> 7;          // / Tv
    int t  = blockIdx.x & (Tv - 1);
    int fi = threadIdx.x;

    const float* inputs = prm.p[0];
    const float* times  = prm.p[1];
    const float* lastv  = prm.p[2];
    const float* freqs  = prm.p[3];

    int gin  = (b*Tv + t)*Fv + fi;     // [B,T,F]
    int gout = (t*Fv + fi)*Bv + b;     // [T,F,B]

    g_xT[gout] = inputs[gin];
    g_lT[gout] = lastv[gin];
    float tv = times[gin];
    float tm = 1.0f / logf(tv + 2.718281828459045f);
    g_Tm[gout]  = tm;
    g_sTm[gout] = 1.0f / (1.0f + expf(-tm));

    float e = expf(-0.5f * freqs[gin]);
    #pragma unroll
    for (int off = 16; off > 0; off >>= 1)
        e += __shfl_down_sync(0xffffffffu, e, off);
    __shared__ float red[2];
    if ((threadIdx.x & 31) == 0) red[threadIdx.x >> 5] = e;
    __syncthreads();
    if (threadIdx.x == 0) g_fw[t*Bv + b] = red[0] + red[1];
}

// ---------------------------------------------------------------------------
// Fast-but-accurate activations (abs err ~1e-7, safe for the recurrence)
// ---------------------------------------------------------------------------
__device__ __forceinline__ float sigf(float x) {
    return __fdividef(1.0f, 1.0f + __expf(-x));
}
__device__ __forceinline__ float tanf_(float x) {
    float e = __expf(-2.0f * fabsf(x));
    float r = __fdividef(1.0f - e, 1.0f + e);
    return copysignf(r, x);
}
__device__ __forceinline__ float eluf(float x) {
    return x > 0.0f ? x : (__expf(x) - 1.0f);
}

// ---------------------------------------------------------------------------
// Main persistent kernel: one CTA per (feature, direction).
// Thread layout: lane = batch b (0..31), warp = column group (j0 = warp*8).
// All weights + state live in shared memory for the entire T loop.
// ---------------------------------------------------------------------------
// smem layout (floats):
//   [0)        smW   : 7 * 4096   (W_j, W_i, W_f, W_o, W_c, W_d, W_decomp)
//   [28672)    smU   : 8 * 64     (U_j, U_i, U_f, U_o, U_c, U_last, U_time, Dw)
//   [29184)    smV   : 11 * 64    (W_cell_i, W_cell_f, W_cell_o, b_j, b_i, b_f,
//                                  b_o, b_c, b_last, b_time, b_d)
//   [29888)    sH    : 32*65
//   [31968)    sC    : 32*65
//   [34048)    sH2   : 32*65
//   [36128)    sC2   : 32*65
//   [38208)    sLT   : 32*65
#define SMEM_FLOATS 40288

__global__ __launch_bounds__(NTHREADS, 1)
void tlstm_kernel(KParams prm, float* __restrict__ out) {
    const int f   = blockIdx.x;
    const int dir = blockIdx.y;
    const int tid = threadIdx.x;
    const int w   = tid >> 5;
    const int b   = tid & 31;
    const int j0  = w * 8;

    extern __shared__ float sm[];
    float* smW = sm;
    float* smU = sm + 28672;
    float* smV = sm + 29184;
    float* sH  = sm + 29888;
    float* sC  = sm + 31968;
    float* sH2 = sm + 34048;
    float* sC2 = sm + 36128;
    float* sLT = sm + 38208;

    // ---- load per-feature weights into smem (coalesced) ----
    #pragma unroll
    for (int m = 0; m < 7; m++) {
        const float* gw = prm.p[12 + m] + (size_t)f * (Hv*Hv);
        for (int i = tid; i < Hv*Hv; i += NTHREADS) smW[m*(Hv*Hv) + i] = gw[i];
    }
    if (tid < Hv) {
        #pragma unroll
        for (int m = 0; m < 8; m++)  smU[m*Hv + tid] = prm.p[4  + m][f*Hv + tid];
        #pragma unroll
        for (int m = 0; m < 11; m++) smV[m*Hv + tid] = prm.p[19 + m][f*Hv + tid];
    }
    // zero h and c (contiguous buffers)
    for (int i = tid; i < 2*Bv*HP; i += NTHREADS) sH[i] = 0.0f;
    __syncthreads();

    const float* crow  = sC  + b*HP;
    const float* hrow  = sH  + b*HP;
    const float* h2row = sH2 + b*HP;

    for (int s = 0; s < Tv; s++) {
        const int t_x   = dir ? (Tv-1-s) : s;
        const int t_tm  = dir ? (s == 0 ? 0 : Tv - s) : s;
        const int t_out = dir ? (Tv-1-s) : s;

        const float xv  = g_xT [(t_x *Fv + f)*Bv + b];
        const float lv  = g_lT [(s   *Fv + f)*Bv + b];
        const float tmv = g_Tm [(t_tm*Fv + f)*Bv + b];
        const float stm = g_sTm[(t_tm*Fv + f)*Bv + b];
        const float fwv = g_fw [ s*Bv + b];

        // ===== phase 1: c @ W_decomp and h @ W_d =====
        float a1[8], a2[8];
        #pragma unroll
        for (int jj = 0; jj < 8; jj++) { a1[jj] = 0.0f; a2[jj] = 0.0f; }
        {
            const float* Wd   = smW + 5*4096;
            const float* Wdec = smW + 6*4096;
            #pragma unroll 4
            for (int k = 0; k < Hv; k++) {
                float ac = crow[k];
                float ah = hrow[k];
                float4 d0 = *(const float4*)(Wdec + k*64 + j0);
                float4 d1 = *(const float4*)(Wdec + k*64 + j0 + 4);
                float4 e0 = *(const float4*)(Wd   + k*64 + j0);
                float4 e1 = *(const float4*)(Wd   + k*64 + j0 + 4);
                a1[0] += ac*d0.x; a1[1] += ac*d0.y; a1[2] += ac*d0.z; a1[3] += ac*d0.w;
                a1[4] += ac*d1.x; a1[5] += ac*d1.y; a1[6] += ac*d1.z; a1[7] += ac*d1.w;
                a2[0] += ah*e0.x; a2[1] += ah*e0.y; a2[2] += ah*e0.z; a2[3] += ah*e0.w;
                a2[4] += ah*e1.x; a2[5] += ah*e1.y; a2[6] += ah*e1.z; a2[7] += ah*e1.w;
            }
        }
        // phase-1 elementwise: c2, last_t, h2 (written to separate buffers; no race)
        #pragma unroll
        for (int jj = 0; jj < 8; jj++) {
            int j = j0 + jj;
            float cv  = sC[b*HP + j];
            float hv  = sH[b*HP + j];
            float dst = tanf_(a1[jj]);                                   // tanh(c@W_decomp)
            float fd1 = sigf(fwv*smU[7*64 + j] + a2[jj] + smV[10*64 + j]); // fdecay(freq,h)
            float ddec = dst * (tmv * fd1);
            float c2  = ddec + (cv - dst + ddec);
            float lt  = eluf(lv*smU[5*64 + j] + smV[8*64 + j]);
            sC2[b*HP + j] = c2;
            sLT[b*HP + j] = lt;
            sH2[b*HP + j] = hv + lt;
        }
        __syncthreads();

        // ===== phase 2: h2 @ {W_j, W_i, W_f, W_o, W_c, W_d} fused =====
        float acc[6][8];
        #pragma unroll
        for (int m = 0; m < 6; m++)
            #pragma unroll
            for (int jj = 0; jj < 8; jj++) acc[m][jj] = 0.0f;

        #pragma unroll 2
        for (int k = 0; k < Hv; k++) {
            float a = h2row[k];
            #pragma unroll
            for (int m = 0; m < 6; m++) {
                float4 w0 = *(const float4*)(smW + m*4096 + k*64 + j0);
                float4 w1 = *(const float4*)(smW + m*4096 + k*64 + j0 + 4);
                acc[m][0] += a*w0.x; acc[m][1] += a*w0.y;
                acc[m][2] += a*w0.z; acc[m][3] += a*w0.w;
                acc[m][4] += a*w1.x; acc[m][5] += a*w1.y;
                acc[m][6] += a*w1.z; acc[m][7] += a*w1.w;
            }
        }

        // phase-2 elementwise: gates, state update, output
        float ho[8];
        #pragma unroll
        for (int jj = 0; jj < 8; jj++) {
            int j = j0 + jj;
            float c2 = sC2[b*HP + j];
            float lt = sLT[b*HP + j];
            float jg  = tanf_(acc[0][jj] + xv*smU[0*64 + j] + smV[3*64 + j]);
            float tg  = sigf(xv*smU[6*64 + j] + stm + smV[9*64 + j]);
            float fd2 = sigf(fwv*smU[7*64 + j] + acc[5][jj] + smV[10*64 + j]);
            float ig  = sigf(xv*smU[1*64 + j] + acc[1][jj] + c2*smV[0*64 + j]
                             + smV[4*64 + j]*fd2);
            float fg  = sigf(xv*smU[2*64 + j] + acc[2][jj] + c2*smV[1*64 + j]
                             + smV[5*64 + j] + jg);
            float fn  = fg*tmv + (1.0f - fg)*fd2;
            float cg  = tanf_(xv*smU[4*64 + j] + acc[4][jj] + smV[7*64 + j]);
            float ct  = (fn + tg)*c2 + ig*jg*tg*cg;
            float og  = sigf(xv*smU[3*64 + j] + acc[3][jj] + tg + lt
                             + ct*smV[2*64 + j] + smV[6*64 + j]);
            float hn  = og * tanf_(ct + lt);
            sH[b*HP + j] = hn;   // safe: phase 2 only reads sH2/sC2/sLT
            sC[b*HP + j] = ct;
            ho[jj] = hn;
        }
        {
            size_t ob = ((size_t)(t_out*Bv + b)*Fv + f)*(2*Hv) + dir*Hv + j0;
            *(float4*)(out + ob)     = make_float4(ho[0], ho[1], ho[2], ho[3]);
            *(float4*)(out + ob + 4) = make_float4(ho[4], ho[5], ho[6], ho[7]);
        }
        __syncthreads();
    }
}

// ---------------------------------------------------------------------------
// Launch
// ---------------------------------------------------------------------------
extern "C" void kernel_launch(void* const* d_in, const int* in_sizes, int n_in,
                              void* d_out, int out_size) {
    KParams prm;
    for (int i = 0; i < 30; i++) prm.p[i] = (const float*)d_in[i];

    cudaFuncSetAttribute(tlstm_kernel,
                         cudaFuncAttributeMaxDynamicSharedMemorySize,
                         SMEM_FLOATS * (int)sizeof(float));

    prologue_kernel<<<Bv*Tv, Fv>>>(prm);
    tlstm_kernel<<<dim3(Fv, 2), NTHREADS, SMEM_FLOATS * sizeof(float)>>>(
        prm, (float*)d_out);
}

// round 2
// speedup vs baseline: 1.0614x; 1.0614x over previous
#include <cuda_runtime.h>
#include <math.h>

// Problem dims (fixed by the reference)
#define Bv 32
#define Tv 128
#define Fv 64
#define Hv 64
#define HP 68            // state row stride: 68 % 32 == 4 -> conflict-free float4 lane loads
#define NTHREADS 512

typedef unsigned long long u64;

// ---------------------------------------------------------------------------
// Scratch (allocation-free): transposed inputs + precomputed time terms
// ---------------------------------------------------------------------------
__device__ float g_xT[Tv*Fv*Bv];   // x   -> [t][f][b]
__device__ float g_lT[Tv*Fv*Bv];   // l   -> [t][f][b]
__device__ float g_Tm[Tv*Fv*Bv];   // 1/log(t+e)
__device__ float g_sTm[Tv*Fv*Bv];  // sigmoid(Tm)
__device__ float g_fw[Tv*Bv];      // sum_f exp(-0.5*freq[b,t,f])

struct KParams { const float* p[30]; };

// ---------------------------------------------------------------------------
// Prologue: transpose + time precompute + cross-feature freq reduction
// ---------------------------------------------------------------------------
__global__ void prologue_kernel(KParams prm) {
    int b  = blockIdx.x >> 7;          // / Tv
    int t  = blockIdx.x & (Tv - 1);
    int fi = threadIdx.x;

    const float* inputs = prm.p[0];
    const float* times  = prm.p[1];
    const float* lastv  = prm.p[2];
    const float* freqs  = prm.p[3];

    int gin  = (b*Tv + t)*Fv + fi;     // [B,T,F]
    int gout = (t*Fv + fi)*Bv + b;     // [T,F,B]

    g_xT[gout] = inputs[gin];
    g_lT[gout] = lastv[gin];
    float tv = times[gin];
    float tm = 1.0f / logf(tv + 2.718281828459045f);
    g_Tm[gout]  = tm;
    g_sTm[gout] = 1.0f / (1.0f + expf(-tm));

    float e = expf(-0.5f * freqs[gin]);
    #pragma unroll
    for (int off = 16; off > 0; off >>= 1)
        e += __shfl_down_sync(0xffffffffu, e, off);
    __shared__ float red[2];
    if ((threadIdx.x & 31) == 0) red[threadIdx.x >> 5] = e;
    __syncthreads();
    if (threadIdx.x == 0) g_fw[t*Bv + b] = red[0] + red[1];
}

// ---------------------------------------------------------------------------
// Packed f32x2 helpers (Blackwell packed fp32 — the only path to fp32 peak)
// ---------------------------------------------------------------------------
__device__ __forceinline__ u64 pk2(float x) {
    u64 r; asm("mov.b64 %0, {%1, %1};" : "=l"(r) : "f"(x)); return r;
}
__device__ __forceinline__ void fma2(u64& d, u64 a, u64 b) {
    asm("fma.rn.f32x2 %0, %1, %2, %0;" : "+l"(d) : "l"(a), "l"(b));
}
__device__ __forceinline__ float2 up2(u64 v) {
    float2 r; asm("mov.b64 {%0, %1}, %2;" : "=f"(r.x), "=f"(r.y) : "l"(v)); return r;
}

// ---------------------------------------------------------------------------
// Fast-but-accurate activations (identical to R1 -> identical numerics)
// ---------------------------------------------------------------------------
__device__ __forceinline__ float sigf(float x) {
    return __fdividef(1.0f, 1.0f + __expf(-x));
}
__device__ __forceinline__ float tanf_(float x) {
    float e = __expf(-2.0f * fabsf(x));
    float r = __fdividef(1.0f - e, 1.0f + e);
    return copysignf(r, x);
}
__device__ __forceinline__ float eluf(float x) {
    return x > 0.0f ? x : (__expf(x) - 1.0f);
}

// ---------------------------------------------------------------------------
// Main persistent kernel: one CTA per (feature, direction).
// 512 threads: lane = batch b (0..31), warp = 4-column group (j0 = warp*4).
// ---------------------------------------------------------------------------
// smem layout (floats):
//   [0)      smW : 7*4096
//   [28672)  smU : 8*64
//   [29184)  smV : 11*64
//   [29888)  sH, sC, sH2, sC2, sLT : 5 * 32*68
#define SMEM_FLOATS (29888 + 5*Bv*HP)

__global__ __launch_bounds__(NTHREADS, 1)
void tlstm_kernel(KParams prm, float* __restrict__ out) {
    const int f   = blockIdx.x;
    const int dir = blockIdx.y;
    const int tid = threadIdx.x;
    const int w   = tid >> 5;
    const int b   = tid & 31;
    const int j0  = w * 4;

    extern __shared__ float sm[];
    float* smW = sm;
    float* smU = sm + 28672;
    float* smV = sm + 29184;
    float* sH  = sm + 29888;
    float* sC  = sH  + Bv*HP;
    float* sH2 = sC  + Bv*HP;
    float* sC2 = sH2 + Bv*HP;
    float* sLT = sC2 + Bv*HP;

    // ---- load per-feature weights into smem (coalesced) ----
    #pragma unroll
    for (int m = 0; m < 7; m++) {
        const float* gw = prm.p[12 + m] + (size_t)f * (Hv*Hv);
        for (int i = tid; i < Hv*Hv; i += NTHREADS) smW[m*(Hv*Hv) + i] = gw[i];
    }
    if (tid < Hv) {
        #pragma unroll
        for (int m = 0; m < 8; m++)  smU[m*Hv + tid] = prm.p[4  + m][f*Hv + tid];
        #pragma unroll
        for (int m = 0; m < 11; m++) smV[m*Hv + tid] = prm.p[19 + m][f*Hv + tid];
    }
    for (int i = tid; i < 2*Bv*HP; i += NTHREADS) sH[i] = 0.0f;
    __syncthreads();

    const float* crow  = sC  + b*HP;
    const float* hrow  = sH  + b*HP;
    const float* h2row = sH2 + b*HP;

    for (int s = 0; s < Tv; s++) {
        const int t_x   = dir ? (Tv-1-s) : s;
        const int t_tm  = dir ? (s == 0 ? 0 : Tv - s) : s;
        const int t_out = dir ? (Tv-1-s) : s;

        const float xv  = g_xT [(t_x *Fv + f)*Bv + b];
        const float lv  = g_lT [(s   *Fv + f)*Bv + b];
        const float tmv = g_Tm [(t_tm*Fv + f)*Bv + b];
        const float stm = g_sTm[(t_tm*Fv + f)*Bv + b];
        const float fwv = g_fw [ s*Bv + b];

        // ===== phase 1: c @ W_decomp and h @ W_d (packed f32x2) =====
        u64 a1[2], a2[2];
        a1[0] = a1[1] = a2[0] = a2[1] = 0ULL;
        {
            const float* Wd   = smW + 5*4096;
            const float* Wdec = smW + 6*4096;
            #pragma unroll 2
            for (int k0 = 0; k0 < Hv; k0 += 4) {
                float4 c4 = *(const float4*)(crow + k0);
                float4 h4 = *(const float4*)(hrow + k0);
                float cc[4] = {c4.x, c4.y, c4.z, c4.w};
                float hh[4] = {h4.x, h4.y, h4.z, h4.w};
                #pragma unroll
                for (int kk = 0; kk < 4; kk++) {
                    int k = k0 + kk;
                    ulonglong2 wd = *(const ulonglong2*)(Wdec + k*64 + j0);
                    ulonglong2 we = *(const ulonglong2*)(Wd   + k*64 + j0);
                    u64 pc = pk2(cc[kk]);
                    u64 ph = pk2(hh[kk]);
                    fma2(a1[0], pc, wd.x); fma2(a1[1], pc, wd.y);
                    fma2(a2[0], ph, we.x); fma2(a2[1], ph, we.y);
                }
            }
        }
        // phase-1 elementwise: c2, last_t, h2
        {
            float2 u0 = up2(a1[0]), u1 = up2(a1[1]);
            float2 v0 = up2(a2[0]), v1 = up2(a2[1]);
            float a1f[4] = {u0.x, u0.y, u1.x, u1.y};
            float a2f[4] = {v0.x, v0.y, v1.x, v1.y};
            float4 cv4 = *(const float4*)(sC + b*HP + j0);
            float4 hv4 = *(const float4*)(sH + b*HP + j0);
            float cva[4] = {cv4.x, cv4.y, cv4.z, cv4.w};
            float hva[4] = {hv4.x, hv4.y, hv4.z, hv4.w};
            float c2a[4], lta[4], h2a[4];
            #pragma unroll
            for (int jj = 0; jj < 4; jj++) {
                int j = j0 + jj;
                float dst  = tanf_(a1f[jj]);
                float fd1  = sigf(fwv*smU[7*64 + j] + a2f[jj] + smV[10*64 + j]);
                float ddec = dst * (tmv * fd1);
                c2a[jj] = ddec + (cva[jj] - dst + ddec);
                lta[jj] = eluf(lv*smU[5*64 + j] + smV[8*64 + j]);
                h2a[jj] = hva[jj] + lta[jj];
            }
            *(float4*)(sC2 + b*HP + j0) = make_float4(c2a[0], c2a[1], c2a[2], c2a[3]);
            *(float4*)(sLT + b*HP + j0) = make_float4(lta[0], lta[1], lta[2], lta[3]);
            *(float4*)(sH2 + b*HP + j0) = make_float4(h2a[0], h2a[1], h2a[2], h2a[3]);
        }
        __syncthreads();

        // ===== phase 2: h2 @ {W_j, W_i, W_f, W_o, W_c, W_d} (packed) =====
        u64 acc[6][2];
        #pragma unroll
        for (int m = 0; m < 6; m++) { acc[m][0] = 0ULL; acc[m][1] = 0ULL; }

        #pragma unroll 2
        for (int k0 = 0; k0 < Hv; k0 += 4) {
            float4 a4 = *(const float4*)(h2row + k0);
            float aa[4] = {a4.x, a4.y, a4.z, a4.w};
            #pragma unroll
            for (int kk = 0; kk < 4; kk++) {
                u64 pa = pk2(aa[kk]);
                const float* wp = smW + (k0 + kk)*64 + j0;
                #pragma unroll
                for (int m = 0; m < 6; m++) {
                    ulonglong2 wv = *(const ulonglong2*)(wp + m*4096);
                    fma2(acc[m][0], pa, wv.x);
                    fma2(acc[m][1], pa, wv.y);
                }
            }
        }

        // phase-2 elementwise: gates, state update, output
        {
            float am[6][4];
            #pragma unroll
            for (int m = 0; m < 6; m++) {
                float2 lo = up2(acc[m][0]), hi = up2(acc[m][1]);
                am[m][0] = lo.x; am[m][1] = lo.y; am[m][2] = hi.x; am[m][3] = hi.y;
            }
            float4 c24 = *(const float4*)(sC2 + b*HP + j0);
            float4 lt4 = *(const float4*)(sLT + b*HP + j0);
            float c2a[4] = {c24.x, c24.y, c24.z, c24.w};
            float lta[4] = {lt4.x, lt4.y, lt4.z, lt4.w};
            float hna[4], cta[4];
            #pragma unroll
            for (int jj = 0; jj < 4; jj++) {
                int j = j0 + jj;
                float c2 = c2a[jj];
                float lt = lta[jj];
                float jg  = tanf_(am[0][jj] + xv*smU[0*64 + j] + smV[3*64 + j]);
                float tg  = sigf(xv*smU[6*64 + j] + stm + smV[9*64 + j]);
                float fd2 = sigf(fwv*smU[7*64 + j] + am[5][jj] + smV[10*64 + j]);
                float ig  = sigf(xv*smU[1*64 + j] + am[1][jj] + c2*smV[0*64 + j]
                                 + smV[4*64 + j]*fd2);
                float fg  = sigf(xv*smU[2*64 + j] + am[2][jj] + c2*smV[1*64 + j]
                                 + smV[5*64 + j] + jg);
                float fn  = fg*tmv + (1.0f - fg)*fd2;
                float cg  = tanf_(xv*smU[4*64 + j] + am[4][jj] + smV[7*64 + j]);
                float ct  = (fn + tg)*c2 + ig*jg*tg*cg;
                float og  = sigf(xv*smU[3*64 + j] + am[3][jj] + tg + lt
                                 + ct*smV[2*64 + j] + smV[6*64 + j]);
                float hn  = og * tanf_(ct + lt);
                hna[jj] = hn; cta[jj] = ct;
            }
            *(float4*)(sH + b*HP + j0) = make_float4(hna[0], hna[1], hna[2], hna[3]);
            *(float4*)(sC + b*HP + j0) = make_float4(cta[0], cta[1], cta[2], cta[3]);
            size_t ob = ((size_t)(t_out*Bv + b)*Fv + f)*(2*Hv) + dir*Hv + j0;
            *(float4*)(out + ob) = make_float4(hna[0], hna[1], hna[2], hna[3]);
        }
        __syncthreads();
    }
}

// ---------------------------------------------------------------------------
// Launch
// ---------------------------------------------------------------------------
extern "C" void kernel_launch(void* const* d_in, const int* in_sizes, int n_in,
                              void* d_out, int out_size) {
    KParams prm;
    for (int i = 0; i < 30; i++) prm.p[i] = (const float*)d_in[i];

    cudaFuncSetAttribute(tlstm_kernel,
                         cudaFuncAttributeMaxDynamicSharedMemorySize,
                         SMEM_FLOATS * (int)sizeof(float));

    prologue_kernel<<<Bv*Tv, Fv>>>(prm);
    tlstm_kernel<<<dim3(Fv, 2), NTHREADS, SMEM_FLOATS * sizeof(float)>>>(
        prm, (float*)d_out);
}

// round 4
// speedup vs baseline: 1.2956x; 1.2206x over previous
#include <cuda_runtime.h>
#include <math.h>

// Problem dims (fixed by the reference)
#define Bv 32
#define Tv 128
#define Fv 64
#define Hv 64
#define BST 36           // state row stride [k][b]: conflict-free STS.128 (36 % 32 == 4)
#define WST 68           // transposed weight row stride [j][k]: conflict-free LDS.128
#define NTHREADS 512

typedef unsigned long long u64;

// ---------------------------------------------------------------------------
// Scratch (allocation-free): transposed inputs + precomputed time terms
// ---------------------------------------------------------------------------
__device__ float g_xT[Tv*Fv*Bv];   // x   -> [t][f][b]
__device__ float g_lT[Tv*Fv*Bv];   // l   -> [t][f][b]
__device__ float g_Tm[Tv*Fv*Bv];   // 1/log(t+e)
__device__ float g_sTm[Tv*Fv*Bv];  // sigmoid(Tm)
__device__ float g_fw[Tv*Bv];      // sum_f exp(-0.5*freq[b,t,f])

struct KParams { const float* p[30]; };

// ---------------------------------------------------------------------------
// Prologue: transpose + time precompute + cross-feature freq reduction
// ---------------------------------------------------------------------------
__global__ void prologue_kernel(KParams prm) {
    int b  = blockIdx.x >> 7;          // / Tv
    int t  = blockIdx.x & (Tv - 1);
    int fi = threadIdx.x;

    const float* inputs = prm.p[0];
    const float* times  = prm.p[1];
    const float* lastv  = prm.p[2];
    const float* freqs  = prm.p[3];

    int gin  = (b*Tv + t)*Fv + fi;     // [B,T,F]
    int gout = (t*Fv + fi)*Bv + b;     // [T,F,B]

    g_xT[gout] = inputs[gin];
    g_lT[gout] = lastv[gin];
    float tv = times[gin];
    float tm = 1.0f / logf(tv + 2.718281828459045f);
    g_Tm[gout]  = tm;
    g_sTm[gout] = 1.0f / (1.0f + expf(-tm));

    float e = expf(-0.5f * freqs[gin]);
    #pragma unroll
    for (int off = 16; off > 0; off >>= 1)
        e += __shfl_down_sync(0xffffffffu, e, off);
    __shared__ float red[2];
    if ((threadIdx.x & 31) == 0) red[threadIdx.x >> 5] = e;
    __syncthreads();
    if (threadIdx.x == 0) g_fw[t*Bv + b] = red[0] + red[1];
}

// ---------------------------------------------------------------------------
// Packed f32x2 helpers
// ---------------------------------------------------------------------------
__device__ __forceinline__ u64 pk2(float x) {
    u64 r; asm("mov.b64 %0, {%1, %1};" : "=l"(r) : "f"(x)); return r;
}
__device__ __forceinline__ void fma2(u64& d, u64 a, u64 b) {
    asm("fma.rn.f32x2 %0, %1, %2, %0;" : "+l"(d) : "l"(a), "l"(b));
}
__device__ __forceinline__ float2 up2(u64 v) {
    float2 r; asm("mov.b64 {%0, %1}, %2;" : "=f"(r.x), "=f"(r.y) : "l"(v)); return r;
}

// ---------------------------------------------------------------------------
// Fast-but-accurate activations (identical to R1/R2 -> identical numerics)
// ---------------------------------------------------------------------------
__device__ __forceinline__ float sigf(float x) {
    return __fdividef(1.0f, 1.0f + __expf(-x));
}
__device__ __forceinline__ float tanf_(float x) {
    float e = __expf(-2.0f * fabsf(x));
    float r = __fdividef(1.0f - e, 1.0f + e);
    return copysignf(r, x);
}
__device__ __forceinline__ float eluf(float x) {
    return x > 0.0f ? x : (__expf(x) - 1.0f);
}

// ---------------------------------------------------------------------------
// Main kernel: one CTA per (feature, direction), 512 threads.
// Warp w: b-group g = w>>1 (4 batches b0=4g..4g+3), j-half = w&1.
// Thread owns output column jcol = (w&1)*32 + lane, for its 4 batches.
// Weights transposed in smem ([j][k], stride WST) -> lane-distinct LDS.128.
// State stored [hidden][b] (stride BST) -> uniform (broadcast) LDS.128 reads,
// conflict-free STS.128 writes; h/c/c2/lt live in registers of the owner.
// ---------------------------------------------------------------------------
#define SMEM_FLOATS (7*Hv*WST + 3*Hv*BST)   // 30464 + 6912 = 37376 floats (146KB)

__global__ __launch_bounds__(NTHREADS, 1)
void tlstm_kernel(KParams prm, float* __restrict__ out) {
    const int f    = blockIdx.x;
    const int dir  = blockIdx.y;
    const int tid  = threadIdx.x;
    const int w    = tid >> 5;
    const int lane = tid & 31;
    const int b0   = (w >> 1) * 4;
    const int jcol = (w & 1) * 32 + lane;

    extern __shared__ float sm[];
    float* wT  = sm;                    // [7][Hv*WST] : wT[m][j*WST + k]
    float* sH  = sm + 7*Hv*WST;         // [Hv][BST]   : h[hidden][b]
    float* sC  = sH + Hv*BST;
    float* sH2 = sC + Hv*BST;

    // ---- transpose per-feature weights into smem ----
    #pragma unroll
    for (int m = 0; m < 7; m++) {
        const float* gw = prm.p[12 + m] + (size_t)f * (Hv*Hv);
        float* wm = wT + m*Hv*WST;
        for (int i = tid; i < Hv*Hv; i += NTHREADS) {
            int k = i >> 6, j = i & 63;
            wm[j*WST + k] = gw[i];
        }
    }
    for (int i = tid; i < 3*Hv*BST; i += NTHREADS) sH[i] = 0.0f;

    // ---- hoist per-column params (loop-invariant) into registers ----
    const float Uj  = prm.p[4 ][f*Hv + jcol];
    const float Ui  = prm.p[5 ][f*Hv + jcol];
    const float Uf  = prm.p[6 ][f*Hv + jcol];
    const float Uo  = prm.p[7 ][f*Hv + jcol];
    const float Uc  = prm.p[8 ][f*Hv + jcol];
    const float Ul  = prm.p[9 ][f*Hv + jcol];
    const float Ut  = prm.p[10][f*Hv + jcol];
    const float Dw  = prm.p[11][f*Hv + jcol];
    const float Wci = prm.p[19][f*Hv + jcol];
    const float Wcf = prm.p[20][f*Hv + jcol];
    const float Wco = prm.p[21][f*Hv + jcol];
    const float bj  = prm.p[22][f*Hv + jcol];
    const float bi  = prm.p[23][f*Hv + jcol];
    const float bf  = prm.p[24][f*Hv + jcol];
    const float bo  = prm.p[25][f*Hv + jcol];
    const float bc  = prm.p[26][f*Hv + jcol];
    const float bl  = prm.p[27][f*Hv + jcol];
    const float bt  = prm.p[28][f*Hv + jcol];
    const float bd  = prm.p[29][f*Hv + jcol];
    __syncthreads();

    float hreg[4] = {0.f,0.f,0.f,0.f};
    float creg[4] = {0.f,0.f,0.f,0.f};

    const float* wDd  = wT + 5*Hv*WST + jcol*WST;   // W_d row for this column
    const float* wDec = wT + 6*Hv*WST + jcol*WST;   // W_decomp row

    for (int s = 0; s < Tv; s++) {
        const int t_x   = dir ? (Tv-1-s) : s;
        const int t_tm  = dir ? (s == 0 ? 0 : Tv - s) : s;
        const int t_out = dir ? (Tv-1-s) : s;

        const float4 xv4 = *(const float4*)&g_xT [(t_x *Fv + f)*Bv + b0];
        const float4 lv4 = *(const float4*)&g_lT [(s   *Fv + f)*Bv + b0];
        const float4 tm4 = *(const float4*)&g_Tm [(t_tm*Fv + f)*Bv + b0];
        const float4 st4 = *(const float4*)&g_sTm[(t_tm*Fv + f)*Bv + b0];
        const float4 fw4 = *(const float4*)&g_fw [ s*Bv + b0];
        const float xva[4] = {xv4.x, xv4.y, xv4.z, xv4.w};
        const float lva[4] = {lv4.x, lv4.y, lv4.z, lv4.w};
        const float tma[4] = {tm4.x, tm4.y, tm4.z, tm4.w};
        const float sta[4] = {st4.x, st4.y, st4.z, st4.w};
        const float fwa[4] = {fw4.x, fw4.y, fw4.z, fw4.w};

        // ===== phase 1: c @ W_decomp, h @ W_d (per column jcol, 4 batches) =====
        u64 aD[2] = {0ULL, 0ULL};   // c@W_decomp, batch pairs (b0,b1),(b2,b3)
        u64 aF[2] = {0ULL, 0ULL};   // h@W_d
        #pragma unroll 4
        for (int k0 = 0; k0 < Hv; k0 += 4) {
            float4 wde = *(const float4*)(wDec + k0);
            float4 wdd = *(const float4*)(wDd  + k0);
            const float wdea[4] = {wde.x, wde.y, wde.z, wde.w};
            const float wdda[4] = {wdd.x, wdd.y, wdd.z, wdd.w};
            #pragma unroll
            for (int kk = 0; kk < 4; kk++) {
                int k = k0 + kk;
                ulonglong2 cu = *(const ulonglong2*)(sC + k*BST + b0);
                ulonglong2 hu = *(const ulonglong2*)(sH + k*BST + b0);
                u64 we2 = pk2(wdea[kk]);
                u64 wd2 = pk2(wdda[kk]);
                fma2(aD[0], cu.x, we2); fma2(aD[1], cu.y, we2);
                fma2(aF[0], hu.x, wd2); fma2(aF[1], hu.y, wd2);
            }
        }
        // phase-1 elementwise (positions (b0..b0+3, jcol)); keep c2/lt in regs
        float c2r[4], ltr[4], h2r[4];
        {
            float2 d0 = up2(aD[0]), d1 = up2(aD[1]);
            float2 f0 = up2(aF[0]), f1 = up2(aF[1]);
            const float a1a[4] = {d0.x, d0.y, d1.x, d1.y};
            const float a2a[4] = {f0.x, f0.y, f1.x, f1.y};
            #pragma unroll
            for (int bb = 0; bb < 4; bb++) {
                float dst  = tanf_(a1a[bb]);
                float fd1  = sigf(fwa[bb]*Dw + a2a[bb] + bd);
                float ddec = dst * (tma[bb] * fd1);
                c2r[bb] = ddec + (creg[bb] - dst + ddec);
                ltr[bb] = eluf(lva[bb]*Ul + bl);
                h2r[bb] = hreg[bb] + ltr[bb];
            }
        }
        *(float4*)(sH2 + jcol*BST + b0) = make_float4(h2r[0], h2r[1], h2r[2], h2r[3]);
        __syncthreads();

        // ===== phase 2: h2 @ {W_j, W_i, W_f, W_o, W_c, W_d} =====
        u64 acc[6][2];
        #pragma unroll
        for (int m = 0; m < 6; m++) { acc[m][0] = 0ULL; acc[m][1] = 0ULL; }

        #pragma unroll 2
        for (int k0 = 0; k0 < Hv; k0 += 4) {
            float4 wv[6];
            #pragma unroll
            for (int m = 0; m < 6; m++)
                wv[m] = *(const float4*)(wT + m*Hv*WST + jcol*WST + k0);
            #pragma unroll
            for (int kk = 0; kk < 4; kk++) {
                ulonglong2 au = *(const ulonglong2*)(sH2 + (k0+kk)*BST + b0);
                #pragma unroll
                for (int m = 0; m < 6; m++) {
                    u64 w2 = pk2(((const float*)&wv[m])[kk]);
                    fma2(acc[m][0], au.x, w2);
                    fma2(acc[m][1], au.y, w2);
                }
            }
        }

        // phase-2 elementwise: gates, state update, output
        {
            float am[6][4];
            #pragma unroll
            for (int m = 0; m < 6; m++) {
                float2 lo = up2(acc[m][0]), hi = up2(acc[m][1]);
                am[m][0] = lo.x; am[m][1] = lo.y; am[m][2] = hi.x; am[m][3] = hi.y;
            }
            #pragma unroll
            for (int bb = 0; bb < 4; bb++) {
                float c2 = c2r[bb];
                float lt = ltr[bb];
                float jg  = tanf_(am[0][bb] + xva[bb]*Uj + bj);
                float tg  = sigf(xva[bb]*Ut + sta[bb] + bt);
                float fd2 = sigf(fwa[bb]*Dw + am[5][bb] + bd);
                float ig  = sigf(xva[bb]*Ui + am[1][bb] + c2*Wci + bi*fd2);
                float fg  = sigf(xva[bb]*Uf + am[2][bb] + c2*Wcf + bf + jg);
                float fn  = fg*tma[bb] + (1.0f - fg)*fd2;
                float cg  = tanf_(xva[bb]*Uc + am[4][bb] + bc);
                float ct  = (fn + tg)*c2 + ig*jg*tg*cg;
                float og  = sigf(xva[bb]*Uo + am[3][bb] + tg + lt + ct*Wco + bo);
                float hn  = og * tanf_(ct + lt);
                hreg[bb] = hn;
                creg[bb] = ct;
                out[((size_t)(t_out*Bv + b0 + bb)*Fv + f)*(2*Hv) + dir*Hv + jcol] = hn;
            }
        }
        *(float4*)(sH + jcol*BST + b0) = make_float4(hreg[0], hreg[1], hreg[2], hreg[3]);
        *(float4*)(sC + jcol*BST + b0) = make_float4(creg[0], creg[1], creg[2], creg[3]);
        __syncthreads();
    }
}

// ---------------------------------------------------------------------------
// Launch
// ---------------------------------------------------------------------------
extern "C" void kernel_launch(void* const* d_in, const int* in_sizes, int n_in,
                              void* d_out, int out_size) {
    KParams prm;
    for (int i = 0; i < 30; i++) prm.p[i] = (const float*)d_in[i];

    cudaFuncSetAttribute(tlstm_kernel,
                         cudaFuncAttributeMaxDynamicSharedMemorySize,
                         SMEM_FLOATS * (int)sizeof(float));

    prologue_kernel<<<Bv*Tv, Fv>>>(prm);
    tlstm_kernel<<<dim3(Fv, 2), NTHREADS, SMEM_FLOATS * sizeof(float)>>>(
        prm, (float*)d_out);
}